// round 15
// baseline (speedup 1.0000x reference)
#include <cuda_runtime.h>
#include <math.h>
#include <stdint.h>

#define MARGIN 0.02f
#define EPS 1e-12f
#define K_INST 4
#define DIM 128
#define NMAX 4096

#define TT 128          // tile edge
#define TTILES 32       // n / TT
#define NBLOCKS 528     // TTILES*(TTILES+1)/2
#define THREADS 256

__device__ double g_tot;
__device__ double g_neg;
__device__ unsigned long long g_nv;
__device__ unsigned int g_ticket;
__device__ int   g_pa[NMAX];
__device__ float g_posp[NMAX * 3];    // pos_dist + MARGIN (plain stores, replay-safe)
__device__ float g_sqn[NMAX];

__device__ __forceinline__ float fsqrt_approx(float x) {
    float r;
    asm("sqrt.approx.f32 %0, %1;" : "=f"(r) : "f"(x));
    return r;
}

__device__ __forceinline__ uint32_t f2tf32(float x) {
    uint32_t r;
    asm("cvt.rna.tf32.f32 %0, %1;" : "=r"(r) : "f"(x));
    return r;
}

#define MMA_TF32(c, a0, a1, a2, a3, b0, b1)                                    \
    asm volatile(                                                              \
        "mma.sync.aligned.m16n8k8.row.col.f32.tf32.tf32.f32 "                  \
        "{%0,%1,%2,%3}, {%4,%5,%6,%7}, {%8,%9}, {%0,%1,%2,%3};"                \
        : "+f"((c)[0]), "+f"((c)[1]), "+f"((c)[2]), "+f"((c)[3])               \
        : "r"(a0), "r"(a1), "r"(a2), "r"(a3), "r"(b0), "r"(b1))

// ---------------------------------------------------------------------------
__global__ void pos_kernel(const float* __restrict__ X, int n) {
    int gwarp = (blockIdx.x * blockDim.x + threadIdx.x) >> 5;
    int lane  = threadIdx.x & 31;
    if (blockIdx.x == 0 && threadIdx.x == 0) {
        g_tot = 0.0; g_neg = 0.0; g_nv = 0ULL; g_ticket = 0u;
    }
    if (gwarp >= n) return;
    int i = gwarp;
    if (lane == 1) g_pa[i] = 0;

    float4 a = ((const float4*)(X + (size_t)i * DIM))[lane];
    float selfsq = a.x * a.x + a.y * a.y + a.z * a.z + a.w * a.w;

    int cs = i & ~(K_INST - 1);
    float dd[K_INST - 1];
    int idx = 0;
    #pragma unroll
    for (int q = 0; q < K_INST; q++) {
        if (cs + q == i) continue;
        float4 b = ((const float4*)(X + (size_t)(cs + q) * DIM))[lane];
        float dx = a.x - b.x, dy = a.y - b.y, dz = a.z - b.z, dw = a.w - b.w;
        dd[idx++] = dx * dx + dy * dy + dz * dz + dw * dw;
    }

    #pragma unroll
    for (int o = 16; o; o >>= 1) {
        selfsq += __shfl_xor_sync(0xFFFFFFFFu, selfsq, o);
        #pragma unroll
        for (int p = 0; p < K_INST - 1; p++)
            dd[p] += __shfl_xor_sync(0xFFFFFFFFu, dd[p], o);
    }

    if (lane == 0) {
        g_sqn[i] = selfsq;
        #pragma unroll
        for (int p = 0; p < K_INST - 1; p++) {
            float d = fsqrt_approx(fmaxf(dd[p], EPS));
            g_posp[i * 3 + p] = d + MARGIN;
        }
    }
}

// ---------------------------------------------------------------------------
// Upper-triangular 128x128 Gram tiles via mma.sync TF32 (cvt.rna inputs).
// Branchless epilogue, column-grouped metadata (4 LDS per 4 cells), dual
// tsum accumulators to break the FADD chain.
__global__ __launch_bounds__(THREADS, 2) void main_kernel(const float* __restrict__ X,
                                                          float* __restrict__ out, int n) {
    // Triangular tile decode
    int bid = blockIdx.x;
    float tf = 2.0f * TTILES + 1.0f;
    int rowT = (int)((tf - sqrtf(tf * tf - 8.0f * (float)bid)) * 0.5f);
    while ((rowT + 1) * TTILES - ((rowT + 1) * rowT) / 2 <= bid) rowT++;
    while (rowT * TTILES - (rowT * (rowT - 1)) / 2 > bid) rowT--;
    int colT = rowT + (bid - (rowT * TTILES - (rowT * (rowT - 1)) / 2));

    __shared__ __align__(16) char As[128 * 128];    // 16 KB
    __shared__ __align__(16) char Bs[128 * 128];    // 16 KB
    __shared__ float sqB[TT];
    __shared__ float ppB[TT * 3];
    __shared__ int   colCnt[TT];
    __shared__ float redT[8], redN[8];
    __shared__ int   redC[8];
    __shared__ int   lastFlag;
    __shared__ int   zsh[THREADS];
    __shared__ double psh[THREADS];

    int tid  = threadIdx.x;
    int lane = tid & 31;
    int w    = tid >> 5;
    int wr   = w >> 1;        // row-band group 0..3 (32 rows each)
    int wc   = w & 1;         // col half 0..1 (64 cols each)
    int gr   = lane >> 2;     // 0..7
    int k4   = lane & 3;      // 0..3
    int rowBase = rowT * TT;
    int colBase = colT * TT;
    bool offdiag = (colT != rowT);

    if (tid < TT) { sqB[tid] = g_sqn[colBase + tid]; colCnt[tid] = 0; }
    #pragma unroll
    for (int rep = 0; rep < 2; rep++) {
        int e = rep * THREADS + tid;
        if (e < TT * 3) ppB[e] = g_posp[colBase * 3 + e];
    }

    float acc[2][8][4];
    #pragma unroll
    for (int b = 0; b < 2; b++)
        #pragma unroll
        for (int t = 0; t < 8; t++)
            #pragma unroll
            for (int q = 0; q < 4; q++) acc[b][t][q] = 0.0f;

    int m0 = wr * 32;
    int grm = gr & 3;

    int row0 = tid >> 2;          // 0..63  (it=0), +64 (it=1)
    int c2   = tid & 3;           // k-chunk 0..3 within 32-k stage

    for (int kc = 0; kc < DIM; kc += 32) {
        if (kc) __syncthreads();

        #pragma unroll
        for (int it = 0; it < 2; it++) {
            int row = row0 + it * 64;
            const float* pA = X + (size_t)(rowBase + row) * DIM + kc + c2 * 8;
            const float* pB = X + (size_t)(colBase + row) * DIM + kc + c2 * 8;
            float4 v = *(const float4*)pA;
            float4 vw = *(const float4*)(pA + 4);
            float4 u = *(const float4*)pB;
            float4 uw = *(const float4*)(pB + 4);
            uint32_t base = (uint32_t)(row * 128 + ((c2 ^ (row & 3)) * 32));
            *(uint4*)(As + base) = make_uint4(
                f2tf32(v.x), f2tf32(vw.x), f2tf32(v.y), f2tf32(vw.y));
            *(uint4*)(As + base + 16) = make_uint4(
                f2tf32(v.z), f2tf32(vw.z), f2tf32(v.w), f2tf32(vw.w));
            *(uint4*)(Bs + base) = make_uint4(
                f2tf32(u.x), f2tf32(uw.x), f2tf32(u.y), f2tf32(uw.y));
            *(uint4*)(Bs + base + 16) = make_uint4(
                f2tf32(u.z), f2tf32(uw.z), f2tf32(u.w), f2tf32(uw.w));
        }
        __syncthreads();

        #pragma unroll
        for (int s = 0; s < 4; s++) {
            uint32_t xs = (uint32_t)(((s ^ grm) * 32) + k4 * 8);
            const char* aB = As + (m0 + gr) * 128 + xs;
            const char* bB = Bs + (wc * 64 + gr) * 128 + xs;
            uint2 fa0 = *(const uint2*)(aB);
            uint2 fa1 = *(const uint2*)(aB + 8 * 128);
            uint2 fa2 = *(const uint2*)(aB + 16 * 128);
            uint2 fa3 = *(const uint2*)(aB + 24 * 128);
            #pragma unroll
            for (int t = 0; t < 8; t++) {
                uint2 fb = *(const uint2*)(bB + t * 1024);
                MMA_TF32(acc[0][t], fa0.x, fa1.x, fa0.y, fa1.y, fb.x, fb.y);
                MMA_TF32(acc[1][t], fa2.x, fa3.x, fa2.y, fa3.y, fb.x, fb.y);
            }
        }
    }

    // --- Fused epilogue (branchless, column-grouped metadata) ---
    int Rl[4];
    float sqa[4], pa3[4][3];
    #pragma unroll
    for (int b = 0; b < 4; b++) {
        Rl[b] = m0 + b * 8 + gr;             // b = band*2 + qv
        int gi = rowBase + Rl[b];
        sqa[b] = g_sqn[gi];
        pa3[b][0] = g_posp[gi * 3 + 0];
        pa3[b][1] = g_posp[gi * 3 + 1];
        pa3[b][2] = g_posp[gi * 3 + 2];
    }

    float tsum0 = 0.0f, tsum1 = 0.0f, nsum = 0.0f;
    int crow[4] = {0, 0, 0, 0};
    int ccol[16];
    #pragma unroll
    for (int e = 0; e < 16; e++) ccol[e] = 0;

    float wn = offdiag ? 2.0f : 1.0f;

    #pragma unroll
    for (int t = 0; t < 8; t++) {
        #pragma unroll
        for (int qh = 0; qh < 2; qh++) {
            int cl = wc * 64 + t * 8 + k4 * 2 + qh;
            int cj = (colBase + cl) >> 2;
            float sqc = sqB[cl];
            float qb0 = ppB[cl * 3], qb1 = ppB[cl * 3 + 1], qb2 = ppB[cl * 3 + 2];
            int e = t * 2 + qh;
            #pragma unroll
            for (int band = 0; band < 2; band++) {
                #pragma unroll
                for (int qv = 0; qv < 2; qv++) {
                    int b = band * 2 + qv;
                    int ci = (rowBase + Rl[b]) >> 2;
                    bool valid = offdiag || (cj != ci);
                    float d2 = fmaxf(sqa[b] + sqc - 2.0f * acc[band][t][qv * 2 + qh], EPS);
                    float d  = fsqrt_approx(d2);
                    float dv = valid ? d : 1e30f;
                    nsum = fmaf(valid ? wn : 0.0f, d, nsum);
                    float t0 = pa3[b][0] - dv;
                    float t1 = pa3[b][1] - dv;
                    float t2 = pa3[b][2] - dv;
                    tsum0 += fmaxf(t0, 0.0f) + fmaxf(t1, 0.0f);
                    tsum1 += fmaxf(t2, 0.0f);
                    crow[b] += (int)(t0 > 0.0f) + (int)(t1 > 0.0f) + (int)(t2 > 0.0f);
                    if (offdiag) {    // block-uniform
                        float u0 = qb0 - d, u1 = qb1 - d, u2 = qb2 - d;
                        tsum1 += fmaxf(u0, 0.0f) + fmaxf(u1, 0.0f);
                        tsum0 += fmaxf(u2, 0.0f);
                        ccol[e] += (int)(u0 > 0.0f) + (int)(u1 > 0.0f) + (int)(u2 > 0.0f);
                    }
                }
            }
        }
    }

    float tsum = tsum0 + tsum1;
    int cnt = 0;
    #pragma unroll
    for (int b = 0; b < 4; b++) cnt += crow[b];
    #pragma unroll
    for (int e = 0; e < 16; e++) cnt += ccol[e];

    // Row-anchor counts: reduce over k4
    #pragma unroll
    for (int b = 0; b < 4; b++) {
        int v = crow[b];
        v += __shfl_xor_sync(0xFFFFFFFFu, v, 1);
        v += __shfl_xor_sync(0xFFFFFFFFu, v, 2);
        if (k4 == 0 && v) atomicAdd(&g_pa[rowBase + Rl[b]], v);
    }

    // Col-anchor counts: reduce over gr
    if (offdiag) {
        #pragma unroll
        for (int e = 0; e < 16; e++) {
            int v = ccol[e];
            v += __shfl_xor_sync(0xFFFFFFFFu, v, 4);
            v += __shfl_xor_sync(0xFFFFFFFFu, v, 8);
            v += __shfl_xor_sync(0xFFFFFFFFu, v, 16);
            if (gr == 0 && v)
                atomicAdd(&colCnt[wc * 64 + (e >> 1) * 8 + k4 * 2 + (e & 1)], v);
        }
    }

    #pragma unroll
    for (int o = 16; o; o >>= 1) {
        tsum += __shfl_xor_sync(0xFFFFFFFFu, tsum, o);
        nsum += __shfl_xor_sync(0xFFFFFFFFu, nsum, o);
        cnt  += __shfl_xor_sync(0xFFFFFFFFu, cnt,  o);
    }
    if (lane == 0) { redT[w] = tsum; redN[w] = nsum; redC[w] = cnt; }
    __syncthreads();

    if (offdiag && tid < TT) {
        int v = colCnt[tid];
        if (v) atomicAdd(&g_pa[colBase + tid], v);
    }
    if (tid == 0) {
        float ts = 0.0f, ns = 0.0f; int cs = 0;
        #pragma unroll
        for (int q = 0; q < 8; q++) { ts += redT[q]; ns += redN[q]; cs += redC[q]; }
        atomicAdd(&g_tot, (double)ts);
        atomicAdd(&g_neg, (double)ns);
        atomicAdd(&g_nv, (unsigned long long)cs);
        __threadfence();
        unsigned int t = atomicAdd(&g_ticket, 1u);
        lastFlag = (t == (unsigned int)(gridDim.x - 1)) ? 1 : 0;
    }
    __syncthreads();

    // --- Last block finalizes the 4 outputs ---
    if (lastFlag) {
        __threadfence();
        int z = 0;
        for (int i2 = tid; i2 < n; i2 += THREADS) z += (g_pa[i2] == 0) ? 1 : 0;
        double ps = 0.0;
        for (int i2 = tid; i2 < n * 3; i2 += THREADS) ps += (double)(g_posp[i2] - MARGIN);
        zsh[tid] = z;
        psh[tid] = ps;
        __syncthreads();
        for (int s = THREADS / 2; s; s >>= 1) {
            if (tid < s) { zsh[tid] += zsh[tid + s]; psh[tid] += psh[tid + s]; }
            __syncthreads();
        }
        if (tid == 0) {
            double nv = (double)g_nv;
            out[0] = (g_nv > 0ULL) ? (float)(g_tot / nv) : 0.0f;
            out[1] = (float)zsh[0] / (float)n;
            out[2] = (float)(psh[0] / ((double)n * (double)(K_INST - 1)));
            out[3] = (float)(g_neg / ((double)n * (double)(n - K_INST)));
        }
    }
}

// ---------------------------------------------------------------------------
extern "C" void kernel_launch(void* const* d_in, const int* in_sizes, int n_in,
                              void* d_out, int out_size) {
    const float* X = (const float*)d_in[0];
    int n = in_sizes[1];           // targets element count = n (4096)

    pos_kernel<<<(n * 32 + 255) / 256, 256>>>(X, n);
    main_kernel<<<NBLOCKS, THREADS>>>(X, (float*)d_out, n);
}

// round 16
// speedup vs baseline: 1.4682x; 1.4682x over previous
#include <cuda_runtime.h>
#include <math.h>
#include <stdint.h>

#define MARGIN 0.02f
#define EPS 1e-12f
#define K_INST 4
#define DIM 128
#define NMAX 4096

#define TT 128          // tile edge
#define TTILES 32       // n / TT
#define NBLOCKS 528     // TTILES*(TTILES+1)/2
#define GRIDB 296       // persistent grid: 2 CTAs/SM x 148 SMs
#define THREADS 256

__device__ double g_tot;
__device__ double g_neg;
__device__ unsigned long long g_nv;
__device__ unsigned int g_ticket;
__device__ int   g_pa[NMAX];
__device__ float g_posp[NMAX * 3];    // pos_dist + MARGIN (plain stores, replay-safe)
__device__ float g_sqn[NMAX];

__device__ __forceinline__ float fsqrt_approx(float x) {
    float r;
    asm("sqrt.approx.f32 %0, %1;" : "=f"(r) : "f"(x));
    return r;
}

__device__ __forceinline__ uint32_t f2tf32(float x) {
    uint32_t r;
    asm("cvt.rna.tf32.f32 %0, %1;" : "=r"(r) : "f"(x));
    return r;
}

#define MMA_TF32(c, a0, a1, a2, a3, b0, b1)                                    \
    asm volatile(                                                              \
        "mma.sync.aligned.m16n8k8.row.col.f32.tf32.tf32.f32 "                  \
        "{%0,%1,%2,%3}, {%4,%5,%6,%7}, {%8,%9}, {%0,%1,%2,%3};"                \
        : "+f"((c)[0]), "+f"((c)[1]), "+f"((c)[2]), "+f"((c)[3])               \
        : "r"(a0), "r"(a1), "r"(a2), "r"(a3), "r"(b0), "r"(b1))

// ---------------------------------------------------------------------------
__global__ void pos_kernel(const float* __restrict__ X, int n) {
    int gwarp = (blockIdx.x * blockDim.x + threadIdx.x) >> 5;
    int lane  = threadIdx.x & 31;
    if (blockIdx.x == 0 && threadIdx.x == 0) {
        g_tot = 0.0; g_neg = 0.0; g_nv = 0ULL; g_ticket = 0u;
    }
    if (gwarp >= n) return;
    int i = gwarp;
    if (lane == 1) g_pa[i] = 0;

    float4 a = ((const float4*)(X + (size_t)i * DIM))[lane];
    float selfsq = a.x * a.x + a.y * a.y + a.z * a.z + a.w * a.w;

    int cs = i & ~(K_INST - 1);
    float dd[K_INST - 1];
    int idx = 0;
    #pragma unroll
    for (int q = 0; q < K_INST; q++) {
        if (cs + q == i) continue;
        float4 b = ((const float4*)(X + (size_t)(cs + q) * DIM))[lane];
        float dx = a.x - b.x, dy = a.y - b.y, dz = a.z - b.z, dw = a.w - b.w;
        dd[idx++] = dx * dx + dy * dy + dz * dz + dw * dw;
    }

    #pragma unroll
    for (int o = 16; o; o >>= 1) {
        selfsq += __shfl_xor_sync(0xFFFFFFFFu, selfsq, o);
        #pragma unroll
        for (int p = 0; p < K_INST - 1; p++)
            dd[p] += __shfl_xor_sync(0xFFFFFFFFu, dd[p], o);
    }

    if (lane == 0) {
        g_sqn[i] = selfsq;
        #pragma unroll
        for (int p = 0; p < K_INST - 1; p++) {
            float d = fsqrt_approx(fmaxf(dd[p], EPS));
            g_posp[i * 3 + p] = d + MARGIN;
        }
    }
}

// ---------------------------------------------------------------------------
// Persistent 296-CTA kernel; each CTA processes <=2 upper-triangular 128x128
// Gram tiles via mma.sync TF32 (cvt.rna inputs). Branchless fused epilogue;
// row metadata staged in smem (low register pressure, no spills).
__global__ __launch_bounds__(THREADS, 2) void main_kernel(const float* __restrict__ X,
                                                          float* __restrict__ out, int n) {
    __shared__ __align__(16) char As[128 * 128];    // 16 KB
    __shared__ __align__(16) char Bs[128 * 128];    // 16 KB
    __shared__ float sqA[TT];
    __shared__ float sqB[TT];
    __shared__ float ppA[TT * 3];
    __shared__ float ppB[TT * 3];
    __shared__ int   colCnt[TT];
    __shared__ float redT[8], redN[8];
    __shared__ int   redC[8];
    __shared__ int   lastFlag;
    __shared__ int   zsh[THREADS];
    __shared__ double psh[THREADS];

    int tid  = threadIdx.x;
    int lane = tid & 31;
    int w    = tid >> 5;
    int wr   = w >> 1;        // row-band group 0..3 (32 rows each)
    int wc   = w & 1;         // col half 0..1 (64 cols each)
    int gr   = lane >> 2;     // 0..7
    int k4   = lane & 3;      // 0..3
    int m0   = wr * 32;
    int grm  = gr & 3;
    int row0 = tid >> 2;      // 0..63  (it=0), +64 (it=1)
    int c2   = tid & 3;       // k-chunk 0..3 within 32-k stage

    #pragma unroll 1
    for (int tile = blockIdx.x; tile < NBLOCKS; tile += GRIDB) {
        // Triangular tile decode
        float tf = 2.0f * TTILES + 1.0f;
        int rowT = (int)((tf - sqrtf(tf * tf - 8.0f * (float)tile)) * 0.5f);
        while ((rowT + 1) * TTILES - ((rowT + 1) * rowT) / 2 <= tile) rowT++;
        while (rowT * TTILES - (rowT * (rowT - 1)) / 2 > tile) rowT--;
        int colT = rowT + (tile - (rowT * TTILES - (rowT * (rowT - 1)) / 2));

        int rowBase = rowT * TT;
        int colBase = colT * TT;
        bool offdiag = (colT != rowT);

        if (tid < TT) {
            sqA[tid] = g_sqn[rowBase + tid];
            sqB[tid] = g_sqn[colBase + tid];
            colCnt[tid] = 0;
        }
        #pragma unroll
        for (int rep = 0; rep < 2; rep++) {
            int e = rep * THREADS + tid;
            if (e < TT * 3) {
                ppA[e] = g_posp[rowBase * 3 + e];
                ppB[e] = g_posp[colBase * 3 + e];
            }
        }

        float acc[2][8][4];
        #pragma unroll
        for (int b = 0; b < 2; b++)
            #pragma unroll
            for (int t = 0; t < 8; t++)
                #pragma unroll
                for (int q = 0; q < 4; q++) acc[b][t][q] = 0.0f;

        for (int kc = 0; kc < DIM; kc += 32) {
            if (kc) __syncthreads();

            #pragma unroll
            for (int it = 0; it < 2; it++) {
                int row = row0 + it * 64;
                const float* pA = X + (size_t)(rowBase + row) * DIM + kc + c2 * 8;
                const float* pB = X + (size_t)(colBase + row) * DIM + kc + c2 * 8;
                float4 v = *(const float4*)pA;
                float4 vw = *(const float4*)(pA + 4);
                float4 u = *(const float4*)pB;
                float4 uw = *(const float4*)(pB + 4);
                uint32_t base = (uint32_t)(row * 128 + ((c2 ^ (row & 3)) * 32));
                *(uint4*)(As + base) = make_uint4(
                    f2tf32(v.x), f2tf32(vw.x), f2tf32(v.y), f2tf32(vw.y));
                *(uint4*)(As + base + 16) = make_uint4(
                    f2tf32(v.z), f2tf32(vw.z), f2tf32(v.w), f2tf32(vw.w));
                *(uint4*)(Bs + base) = make_uint4(
                    f2tf32(u.x), f2tf32(uw.x), f2tf32(u.y), f2tf32(uw.y));
                *(uint4*)(Bs + base + 16) = make_uint4(
                    f2tf32(u.z), f2tf32(uw.z), f2tf32(u.w), f2tf32(uw.w));
            }
            __syncthreads();

            #pragma unroll
            for (int s = 0; s < 4; s++) {
                uint32_t xs = (uint32_t)(((s ^ grm) * 32) + k4 * 8);
                const char* aB = As + (m0 + gr) * 128 + xs;
                const char* bB = Bs + (wc * 64 + gr) * 128 + xs;
                uint2 fa0 = *(const uint2*)(aB);
                uint2 fa1 = *(const uint2*)(aB + 8 * 128);
                uint2 fa2 = *(const uint2*)(aB + 16 * 128);
                uint2 fa3 = *(const uint2*)(aB + 24 * 128);
                #pragma unroll
                for (int t = 0; t < 8; t++) {
                    uint2 fb = *(const uint2*)(bB + t * 1024);
                    MMA_TF32(acc[0][t], fa0.x, fa1.x, fa0.y, fa1.y, fb.x, fb.y);
                    MMA_TF32(acc[1][t], fa2.x, fa3.x, fa2.y, fa3.y, fb.x, fb.y);
                }
            }
        }

        // --- Fused epilogue (branchless, R13 structure, smem row metadata) ---
        float tsum = 0.0f, nsum = 0.0f;
        int crow[4] = {0, 0, 0, 0};
        int ccol[16];
        #pragma unroll
        for (int e = 0; e < 16; e++) ccol[e] = 0;

        float wn = offdiag ? 2.0f : 1.0f;

        #pragma unroll
        for (int band = 0; band < 2; band++) {
            #pragma unroll
            for (int q = 0; q < 4; q++) {
                int b = band * 2 + (q >> 1);
                int rl = m0 + b * 8 + gr;
                int ci = (rowBase + rl) >> 2;
                float sqi = sqA[rl];
                float pp0 = ppA[rl * 3], pp1 = ppA[rl * 3 + 1], pp2 = ppA[rl * 3 + 2];
                #pragma unroll
                for (int t = 0; t < 8; t++) {
                    int cl = wc * 64 + t * 8 + k4 * 2 + (q & 1);
                    int gj = colBase + cl;
                    bool valid = offdiag || ((gj >> 2) != ci);
                    float d2 = fmaxf(sqi + sqB[cl] - 2.0f * acc[band][t][q], EPS);
                    float d  = fsqrt_approx(d2);
                    float dv = valid ? d : 1e30f;
                    nsum = fmaf(valid ? wn : 0.0f, d, nsum);
                    float t0 = pp0 - dv, t1 = pp1 - dv, t2 = pp2 - dv;
                    tsum += fmaxf(t0, 0.0f);
                    tsum += fmaxf(t1, 0.0f);
                    tsum += fmaxf(t2, 0.0f);
                    crow[b] += (int)(t0 > 0.0f) + (int)(t1 > 0.0f) + (int)(t2 > 0.0f);
                    if (offdiag) {   // block-uniform branch
                        float u0 = ppB[cl * 3]     - d;
                        float u1 = ppB[cl * 3 + 1] - d;
                        float u2 = ppB[cl * 3 + 2] - d;
                        tsum += fmaxf(u0, 0.0f);
                        tsum += fmaxf(u1, 0.0f);
                        tsum += fmaxf(u2, 0.0f);
                        ccol[t * 2 + (q & 1)] +=
                            (int)(u0 > 0.0f) + (int)(u1 > 0.0f) + (int)(u2 > 0.0f);
                    }
                }
            }
        }

        int cnt = 0;
        #pragma unroll
        for (int b = 0; b < 4; b++) cnt += crow[b];
        #pragma unroll
        for (int e = 0; e < 16; e++) cnt += ccol[e];

        // Row-anchor counts: reduce over k4
        #pragma unroll
        for (int b = 0; b < 4; b++) {
            int v = crow[b];
            v += __shfl_xor_sync(0xFFFFFFFFu, v, 1);
            v += __shfl_xor_sync(0xFFFFFFFFu, v, 2);
            if (k4 == 0 && v) atomicAdd(&g_pa[rowBase + m0 + b * 8 + gr], v);
        }

        // Col-anchor counts: reduce over gr
        if (offdiag) {
            #pragma unroll
            for (int e = 0; e < 16; e++) {
                int v = ccol[e];
                v += __shfl_xor_sync(0xFFFFFFFFu, v, 4);
                v += __shfl_xor_sync(0xFFFFFFFFu, v, 8);
                v += __shfl_xor_sync(0xFFFFFFFFu, v, 16);
                if (gr == 0 && v)
                    atomicAdd(&colCnt[wc * 64 + (e >> 1) * 8 + k4 * 2 + (e & 1)], v);
            }
        }

        #pragma unroll
        for (int o = 16; o; o >>= 1) {
            tsum += __shfl_xor_sync(0xFFFFFFFFu, tsum, o);
            nsum += __shfl_xor_sync(0xFFFFFFFFu, nsum, o);
            cnt  += __shfl_xor_sync(0xFFFFFFFFu, cnt,  o);
        }
        if (lane == 0) { redT[w] = tsum; redN[w] = nsum; redC[w] = cnt; }
        __syncthreads();

        if (offdiag && tid < TT) {
            int v = colCnt[tid];
            if (v) atomicAdd(&g_pa[colBase + tid], v);
        }
        if (tid == 0) {
            float ts = 0.0f, ns = 0.0f; int cs = 0;
            #pragma unroll
            for (int q = 0; q < 8; q++) { ts += redT[q]; ns += redN[q]; cs += redC[q]; }
            atomicAdd(&g_tot, (double)ts);
            atomicAdd(&g_neg, (double)ns);
            atomicAdd(&g_nv, (unsigned long long)cs);
            __threadfence();
            unsigned int t = atomicAdd(&g_ticket, 1u);
            lastFlag = (t == (unsigned int)(NBLOCKS - 1)) ? 1 : 0;
        }
        __syncthreads();

        // --- Globally-last tile finalizes the 4 outputs ---
        if (lastFlag) {
            __threadfence();
            int z = 0;
            for (int i2 = tid; i2 < n; i2 += THREADS) z += (g_pa[i2] == 0) ? 1 : 0;
            double ps = 0.0;
            for (int i2 = tid; i2 < n * 3; i2 += THREADS)
                ps += (double)(g_posp[i2] - MARGIN);
            zsh[tid] = z;
            psh[tid] = ps;
            __syncthreads();
            for (int s = THREADS / 2; s; s >>= 1) {
                if (tid < s) { zsh[tid] += zsh[tid + s]; psh[tid] += psh[tid + s]; }
                __syncthreads();
            }
            if (tid == 0) {
                double nv = (double)g_nv;
                out[0] = (g_nv > 0ULL) ? (float)(g_tot / nv) : 0.0f;
                out[1] = (float)zsh[0] / (float)n;
                out[2] = (float)(psh[0] / ((double)n * (double)(K_INST - 1)));
                out[3] = (float)(g_neg / ((double)n * (double)(n - K_INST)));
            }
        }
        __syncthreads();   // protect smem reuse by next tile iteration
    }
}

// ---------------------------------------------------------------------------
extern "C" void kernel_launch(void* const* d_in, const int* in_sizes, int n_in,
                              void* d_out, int out_size) {
    const float* X = (const float*)d_in[0];
    int n = in_sizes[1];           // targets element count = n (4096)

    pos_kernel<<<(n * 32 + 255) / 256, 256>>>(X, n);
    main_kernel<<<GRIDB, THREADS>>>(X, (float*)d_out, n);
}

// round 17
// speedup vs baseline: 1.5097x; 1.0282x over previous
#include <cuda_runtime.h>
#include <math.h>
#include <stdint.h>

#define MARGIN 0.02f
#define EPS 1e-12f
#define K_INST 4
#define DIM 128
#define NMAX 4096

#define TT 128          // tile edge
#define TTILES 32       // n / TT
#define NBLOCKS 528     // TTILES*(TTILES+1)/2
#define GRIDB 296       // persistent grid: 2 CTAs/SM x 148 SMs
#define THREADS 256

__device__ double g_tot;
__device__ double g_neg;
__device__ unsigned int g_ticket;
__device__ int   g_pa[NMAX];
__device__ float g_posp[NMAX * 3];    // pos_dist + MARGIN (plain stores, replay-safe)
__device__ float g_sqn[NMAX];

__device__ __forceinline__ float fsqrt_approx(float x) {
    float r;
    asm("sqrt.approx.f32 %0, %1;" : "=f"(r) : "f"(x));
    return r;
}

__device__ __forceinline__ uint32_t f2tf32(float x) {
    uint32_t r;
    asm("cvt.rna.tf32.f32 %0, %1;" : "=r"(r) : "f"(x));
    return r;
}

#define MMA_TF32(c, a0, a1, a2, a3, b0, b1)                                    \
    asm volatile(                                                              \
        "mma.sync.aligned.m16n8k8.row.col.f32.tf32.tf32.f32 "                  \
        "{%0,%1,%2,%3}, {%4,%5,%6,%7}, {%8,%9}, {%0,%1,%2,%3};"                \
        : "+f"((c)[0]), "+f"((c)[1]), "+f"((c)[2]), "+f"((c)[3])               \
        : "r"(a0), "r"(a1), "r"(a2), "r"(a3), "r"(b0), "r"(b1))

// ---------------------------------------------------------------------------
__global__ void pos_kernel(const float* __restrict__ X, int n) {
    int gwarp = (blockIdx.x * blockDim.x + threadIdx.x) >> 5;
    int lane  = threadIdx.x & 31;
    if (blockIdx.x == 0 && threadIdx.x == 0) {
        g_tot = 0.0; g_neg = 0.0; g_ticket = 0u;
    }
    if (gwarp >= n) return;
    int i = gwarp;
    if (lane == 1) g_pa[i] = 0;

    float4 a = ((const float4*)(X + (size_t)i * DIM))[lane];
    float selfsq = a.x * a.x + a.y * a.y + a.z * a.z + a.w * a.w;

    int cs = i & ~(K_INST - 1);
    float dd[K_INST - 1];
    int idx = 0;
    #pragma unroll
    for (int q = 0; q < K_INST; q++) {
        if (cs + q == i) continue;
        float4 b = ((const float4*)(X + (size_t)(cs + q) * DIM))[lane];
        float dx = a.x - b.x, dy = a.y - b.y, dz = a.z - b.z, dw = a.w - b.w;
        dd[idx++] = dx * dx + dy * dy + dz * dz + dw * dw;
    }

    #pragma unroll
    for (int o = 16; o; o >>= 1) {
        selfsq += __shfl_xor_sync(0xFFFFFFFFu, selfsq, o);
        #pragma unroll
        for (int p = 0; p < K_INST - 1; p++)
            dd[p] += __shfl_xor_sync(0xFFFFFFFFu, dd[p], o);
    }

    if (lane == 0) {
        g_sqn[i] = selfsq;
        #pragma unroll
        for (int p = 0; p < K_INST - 1; p++) {
            float d = fsqrt_approx(fmaxf(dd[p], EPS));
            g_posp[i * 3 + p] = d + MARGIN;
        }
    }
}

// ---------------------------------------------------------------------------
// Persistent 296-CTA kernel; 128x128 upper-triangular Gram tiles via
// mma.sync TF32. Specialized offdiag (no validity logic) / diag epilogues;
// global triplet count derived from g_pa in the finalizer.
__global__ __launch_bounds__(THREADS, 2) void main_kernel(const float* __restrict__ X,
                                                          float* __restrict__ out, int n) {
    __shared__ __align__(16) char As[128 * 128];    // 16 KB
    __shared__ __align__(16) char Bs[128 * 128];    // 16 KB
    __shared__ float sqA[TT];
    __shared__ float sqB[TT];
    __shared__ float ppA[TT * 3];
    __shared__ float ppB[TT * 3];
    __shared__ int   colCnt[TT];
    __shared__ float redT[8], redN[8];
    __shared__ int   lastFlag;
    __shared__ int   zsh[THREADS];
    __shared__ int   csh[THREADS];
    __shared__ double psh[THREADS];

    int tid  = threadIdx.x;
    int lane = tid & 31;
    int w    = tid >> 5;
    int wr   = w >> 1;        // row-band group 0..3 (32 rows each)
    int wc   = w & 1;         // col half 0..1 (64 cols each)
    int gr   = lane >> 2;     // 0..7
    int k4   = lane & 3;      // 0..3
    int m0   = wr * 32;
    int grm  = gr & 3;
    int row0 = tid >> 2;      // 0..63  (it=0), +64 (it=1)
    int c2   = tid & 3;       // k-chunk 0..3 within 32-k stage

    #pragma unroll 1
    for (int tile = blockIdx.x; tile < NBLOCKS; tile += GRIDB) {
        // Triangular tile decode
        float tf = 2.0f * TTILES + 1.0f;
        int rowT = (int)((tf - sqrtf(tf * tf - 8.0f * (float)tile)) * 0.5f);
        while ((rowT + 1) * TTILES - ((rowT + 1) * rowT) / 2 <= tile) rowT++;
        while (rowT * TTILES - (rowT * (rowT - 1)) / 2 > tile) rowT--;
        int colT = rowT + (tile - (rowT * TTILES - (rowT * (rowT - 1)) / 2));

        int rowBase = rowT * TT;
        int colBase = colT * TT;
        bool offdiag = (colT != rowT);

        if (tid < TT) {
            sqA[tid] = g_sqn[rowBase + tid];
            sqB[tid] = g_sqn[colBase + tid];
            colCnt[tid] = 0;
        }
        #pragma unroll
        for (int rep = 0; rep < 2; rep++) {
            int e = rep * THREADS + tid;
            if (e < TT * 3) {
                ppA[e] = g_posp[rowBase * 3 + e];
                ppB[e] = g_posp[colBase * 3 + e];
            }
        }

        float acc[2][8][4];
        #pragma unroll
        for (int b = 0; b < 2; b++)
            #pragma unroll
            for (int t = 0; t < 8; t++)
                #pragma unroll
                for (int q = 0; q < 4; q++) acc[b][t][q] = 0.0f;

        for (int kc = 0; kc < DIM; kc += 32) {
            if (kc) __syncthreads();

            #pragma unroll
            for (int it = 0; it < 2; it++) {
                int row = row0 + it * 64;
                const float* pA = X + (size_t)(rowBase + row) * DIM + kc + c2 * 8;
                const float* pB = X + (size_t)(colBase + row) * DIM + kc + c2 * 8;
                float4 v = *(const float4*)pA;
                float4 vw = *(const float4*)(pA + 4);
                float4 u = *(const float4*)pB;
                float4 uw = *(const float4*)(pB + 4);
                uint32_t base = (uint32_t)(row * 128 + ((c2 ^ (row & 3)) * 32));
                *(uint4*)(As + base) = make_uint4(
                    f2tf32(v.x), f2tf32(vw.x), f2tf32(v.y), f2tf32(vw.y));
                *(uint4*)(As + base + 16) = make_uint4(
                    f2tf32(v.z), f2tf32(vw.z), f2tf32(v.w), f2tf32(vw.w));
                *(uint4*)(Bs + base) = make_uint4(
                    f2tf32(u.x), f2tf32(uw.x), f2tf32(u.y), f2tf32(uw.y));
                *(uint4*)(Bs + base + 16) = make_uint4(
                    f2tf32(u.z), f2tf32(uw.z), f2tf32(u.w), f2tf32(uw.w));
            }
            __syncthreads();

            #pragma unroll
            for (int s = 0; s < 4; s++) {
                uint32_t xs = (uint32_t)(((s ^ grm) * 32) + k4 * 8);
                const char* aB = As + (m0 + gr) * 128 + xs;
                const char* bB = Bs + (wc * 64 + gr) * 128 + xs;
                uint2 fa0 = *(const uint2*)(aB);
                uint2 fa1 = *(const uint2*)(aB + 8 * 128);
                uint2 fa2 = *(const uint2*)(aB + 16 * 128);
                uint2 fa3 = *(const uint2*)(aB + 24 * 128);
                #pragma unroll
                for (int t = 0; t < 8; t++) {
                    uint2 fb = *(const uint2*)(bB + t * 1024);
                    MMA_TF32(acc[0][t], fa0.x, fa1.x, fa0.y, fa1.y, fb.x, fb.y);
                    MMA_TF32(acc[1][t], fa2.x, fa3.x, fa2.y, fa3.y, fb.x, fb.y);
                }
            }
        }

        // --- Fused epilogue, specialized paths ---
        float tsum0 = 0.0f, tsum1 = 0.0f, nsum = 0.0f;
        int crow[4] = {0, 0, 0, 0};
        int ccol[16];
        #pragma unroll
        for (int e = 0; e < 16; e++) ccol[e] = 0;

        if (offdiag) {
            // All cells valid: no masks, both anchor views, nsum scaled x2 at end.
            #pragma unroll
            for (int band = 0; band < 2; band++) {
                #pragma unroll
                for (int q = 0; q < 4; q++) {
                    int b = band * 2 + (q >> 1);
                    int rl = m0 + b * 8 + gr;
                    float sqi = sqA[rl];
                    float pp0 = ppA[rl * 3], pp1 = ppA[rl * 3 + 1], pp2 = ppA[rl * 3 + 2];
                    #pragma unroll
                    for (int t = 0; t < 8; t++) {
                        int cl = wc * 64 + t * 8 + k4 * 2 + (q & 1);
                        float d2 = fmaxf(fmaf(acc[band][t][q], -2.0f, sqi) + sqB[cl], EPS);
                        float d  = fsqrt_approx(d2);
                        nsum += d;
                        float t0 = pp0 - d, t1 = pp1 - d, t2 = pp2 - d;
                        tsum0 += fmaxf(t0, 0.0f) + fmaxf(t1, 0.0f);
                        tsum1 += fmaxf(t2, 0.0f);
                        crow[b] += (int)(t0 > 0.0f) + (int)(t1 > 0.0f) + (int)(t2 > 0.0f);
                        float u0 = ppB[cl * 3]     - d;
                        float u1 = ppB[cl * 3 + 1] - d;
                        float u2 = ppB[cl * 3 + 2] - d;
                        tsum1 += fmaxf(u0, 0.0f) + fmaxf(u1, 0.0f);
                        tsum0 += fmaxf(u2, 0.0f);
                        ccol[t * 2 + (q & 1)] +=
                            (int)(u0 > 0.0f) + (int)(u1 > 0.0f) + (int)(u2 > 0.0f);
                    }
                }
            }
            nsum *= 2.0f;
        } else {
            // Diagonal tile: per-cell validity, single (row) view.
            #pragma unroll
            for (int band = 0; band < 2; band++) {
                #pragma unroll
                for (int q = 0; q < 4; q++) {
                    int b = band * 2 + (q >> 1);
                    int rl = m0 + b * 8 + gr;
                    int ci = (rowBase + rl) >> 2;
                    float sqi = sqA[rl];
                    float pp0 = ppA[rl * 3], pp1 = ppA[rl * 3 + 1], pp2 = ppA[rl * 3 + 2];
                    #pragma unroll
                    for (int t = 0; t < 8; t++) {
                        int cl = wc * 64 + t * 8 + k4 * 2 + (q & 1);
                        bool valid = ((colBase + cl) >> 2) != ci;
                        float d2 = fmaxf(fmaf(acc[band][t][q], -2.0f, sqi) + sqB[cl], EPS);
                        float d  = fsqrt_approx(d2);
                        float dv = valid ? d : 1e30f;
                        nsum += valid ? d : 0.0f;
                        float t0 = pp0 - dv, t1 = pp1 - dv, t2 = pp2 - dv;
                        tsum0 += fmaxf(t0, 0.0f) + fmaxf(t1, 0.0f);
                        tsum1 += fmaxf(t2, 0.0f);
                        crow[b] += (int)(t0 > 0.0f) + (int)(t1 > 0.0f) + (int)(t2 > 0.0f);
                    }
                }
            }
        }

        float tsum = tsum0 + tsum1;

        // Row-anchor counts: reduce over k4
        #pragma unroll
        for (int b = 0; b < 4; b++) {
            int v = crow[b];
            v += __shfl_xor_sync(0xFFFFFFFFu, v, 1);
            v += __shfl_xor_sync(0xFFFFFFFFu, v, 2);
            if (k4 == 0 && v) atomicAdd(&g_pa[rowBase + m0 + b * 8 + gr], v);
        }

        // Col-anchor counts: reduce over gr
        if (offdiag) {
            #pragma unroll
            for (int e = 0; e < 16; e++) {
                int v = ccol[e];
                v += __shfl_xor_sync(0xFFFFFFFFu, v, 4);
                v += __shfl_xor_sync(0xFFFFFFFFu, v, 8);
                v += __shfl_xor_sync(0xFFFFFFFFu, v, 16);
                if (gr == 0 && v)
                    atomicAdd(&colCnt[wc * 64 + (e >> 1) * 8 + k4 * 2 + (e & 1)], v);
            }
        }

        #pragma unroll
        for (int o = 16; o; o >>= 1) {
            tsum += __shfl_xor_sync(0xFFFFFFFFu, tsum, o);
            nsum += __shfl_xor_sync(0xFFFFFFFFu, nsum, o);
        }
        if (lane == 0) { redT[w] = tsum; redN[w] = nsum; }
        __syncthreads();

        if (offdiag && tid < TT) {
            int v = colCnt[tid];
            if (v) atomicAdd(&g_pa[colBase + tid], v);
        }
        if (tid == 0) {
            float ts = 0.0f, ns = 0.0f;
            #pragma unroll
            for (int q = 0; q < 8; q++) { ts += redT[q]; ns += redN[q]; }
            atomicAdd(&g_tot, (double)ts);
            atomicAdd(&g_neg, (double)ns);
            __threadfence();
            unsigned int t = atomicAdd(&g_ticket, 1u);
            lastFlag = (t == (unsigned int)(NBLOCKS - 1)) ? 1 : 0;
        }
        __syncthreads();

        // --- Globally-last tile finalizes the 4 outputs ---
        if (lastFlag) {
            __threadfence();
            int z = 0, c = 0;
            for (int i2 = tid; i2 < n; i2 += THREADS) {
                int pv = g_pa[i2];
                z += (pv == 0) ? 1 : 0;
                c += pv;
            }
            double ps = 0.0;
            for (int i2 = tid; i2 < n * 3; i2 += THREADS)
                ps += (double)(g_posp[i2] - MARGIN);
            zsh[tid] = z;
            csh[tid] = c;
            psh[tid] = ps;
            __syncthreads();
            for (int s = THREADS / 2; s; s >>= 1) {
                if (tid < s) {
                    zsh[tid] += zsh[tid + s];
                    csh[tid] += csh[tid + s];
                    psh[tid] += psh[tid + s];
                }
                __syncthreads();
            }
            if (tid == 0) {
                int nv = csh[0];
                out[0] = (nv > 0) ? (float)(g_tot / (double)nv) : 0.0f;
                out[1] = (float)zsh[0] / (float)n;
                out[2] = (float)(psh[0] / ((double)n * (double)(K_INST - 1)));
                out[3] = (float)(g_neg / ((double)n * (double)(n - K_INST)));
            }
        }
        __syncthreads();   // protect smem reuse by next tile iteration
    }
}

// ---------------------------------------------------------------------------
extern "C" void kernel_launch(void* const* d_in, const int* in_sizes, int n_in,
                              void* d_out, int out_size) {
    const float* X = (const float*)d_in[0];
    int n = in_sizes[1];           // targets element count = n (4096)

    pos_kernel<<<(n * 32 + 255) / 256, 256>>>(X, n);
    main_kernel<<<GRIDB, THREADS>>>(X, (float*)d_out, n);
}